// round 7
// baseline (speedup 1.0000x reference)
#include <cuda_runtime.h>
#include <math.h>

// Fixed problem shape (from setup_inputs)
#define Bb 2
#define L  2048
#define H  64
#define P  64
#define NS 128
#define CS 256
#define NC 8

// ---------------- scratch (static device globals; no runtime alloc) -------
__device__ float g_dt   [Bb*H*NC*CS];            // softplus(dt+bias)
__device__ float g_dacs [Bb*H*NC*CS];            // cumsum(dA) within chunk
__device__ float g_dAl  [Bb*H*NC];               // last cumsum per chunk
__device__ float g_states[(size_t)Bb*NC*H*P*NS]; // chunk end-state contribs
__device__ float g_prev  [(size_t)Bb*NC*H*P*NS]; // propagated prev states
__device__ float g_CB   [(size_t)Bb*NC*CS*CS];   // C @ B^T per (b,c)
__device__ float g_xt   [(size_t)Bb*H*P*L];      // x transposed: [b,h,p,l]

// packed dual-FMA: {c.x,c.y} += {a.x,a.y}*{b.x,b.y}  (one FFMA2 instruction)
__device__ __forceinline__ float2 fma2(float2 a, float2 b, float2 c) {
    unsigned long long ua = *reinterpret_cast<unsigned long long*>(&a);
    unsigned long long ub = *reinterpret_cast<unsigned long long*>(&b);
    unsigned long long uc = *reinterpret_cast<unsigned long long*>(&c);
    asm("fma.rn.f32x2 %0, %1, %2, %0;" : "+l"(uc) : "l"(ua), "l"(ub));
    return *reinterpret_cast<float2*>(&uc);
}

// ---------------- K0: transpose x -> xt[b,h,p,l] ---------------------------
__global__ void k_xt(const float* __restrict__ x) {
    __shared__ float tile[32][33];
    int bc = blockIdx.z;
    int b = bc >> 3, c = bc & 7;
    int hp0 = blockIdx.x * 32, s0 = blockIdx.y * 32;
    int tx = threadIdx.x, ty = threadIdx.y;   // 32 x 8
#pragma unroll
    for (int j = 0; j < 4; j++)
        tile[ty + 8 * j][tx] = x[((size_t)(b * L + c * CS + s0 + ty + 8 * j)) * 4096 + hp0 + tx];
    __syncthreads();
#pragma unroll
    for (int j = 0; j < 4; j++)
        g_xt[((size_t)b * 4096 + hp0 + ty + 8 * j) * L + c * CS + s0 + tx] = tile[tx][ty + 8 * j];
}

// ---------------- K1: dt softplus + per-chunk cumsum ----------------------
__global__ void k_dt(const float* __restrict__ dt, const float* __restrict__ A,
                     const float* __restrict__ dtb) {
    int idx = blockIdx.x;               // b*H*NC
    int c = idx % NC;
    int h = (idx / NC) % H;
    int b = idx / (NC * H);
    int s = threadIdx.x;
    int lg = c * CS + s;

    float v = dt[((size_t)b * L + lg) * H + h] + dtb[h];
    float sp = (v > 20.f) ? v : log1pf(__expf(v));
    float dA = sp * A[h];

    __shared__ float sm[CS];
    sm[s] = dA;
    __syncthreads();
#pragma unroll
    for (int off = 1; off < CS; off <<= 1) {
        float pv = (s >= off) ? sm[s - off] : 0.f;
        __syncthreads();
        sm[s] += pv;
        __syncthreads();
    }
    int base = ((b * H + h) * NC + c) * CS;
    g_dt[base + s] = sp;
    g_dacs[base + s] = sm[s];
    if (s == CS - 1) g_dAl[(b * H + h) * NC + c] = sm[s];
}

// ---------------- K2: chunk_state, head-batched GEMM per (b,c) ------------
// out[(h,p), n] = sum_s (w[h,s]*x[s,h,p]) * B[s, n]   M=4096 N=128 K=256
// tile 128(m: 2 heads) x 64(n), k-tile 32, register-prefetch pipelined
__global__ void __launch_bounds__(256, 2) k_state2(const float* __restrict__ Bm) {
    int blk = blockIdx.x;
    int nt = blk & 1; blk >>= 1;
    int mt = blk & 31; blk >>= 5;
    int bc = blk;                      // 0..15
    int b = bc >> 3, c = bc & 7;
    int h0 = mt * 2, m0 = mt * 128;

    __shared__ float As[128][34];      // x*w tile [m][k]
    __shared__ float Bs[64][34];       // B tile   [n][k]
    __shared__ float ws[2][CS];

    int t = threadIdx.x, ty = t >> 4, tx = t & 15;
#pragma unroll
    for (int hh = 0; hh < 2; hh++) {
        int dbase = ((b * H + h0 + hh) * NC + c) * CS;
        float dlast = g_dAl[(b * H + h0 + hh) * NC + c];
        ws[hh][t] = __expf(dlast - g_dacs[dbase + t]) * g_dt[dbase + t];
    }

    // prefetch mapping:
    //  A: m = t>>1, k0 = (t&1)*16, 4 x float4 along k (from xt, s-contiguous)
    //  B: k = (t>>4) (+16*i), n4 = (t&15)*4, 2 x float4 along n
    int am = t >> 1, ak0 = (t & 1) * 16;
    int bk = t >> 4, bn4 = (t & 15) * 4;
    const float4* xa_p = (const float4*)(g_xt + ((size_t)b * 4096 + m0 + am) * L + c * CS + ak0);
    const float*  bm_p = Bm + (size_t)(b * L + c * CS) * NS + nt * 64 + bn4;

    float4 xa[4], bb[2];
#pragma unroll
    for (int i = 0; i < 4; i++) xa[i] = xa_p[i];
#pragma unroll
    for (int i = 0; i < 2; i++) bb[i] = *(const float4*)(bm_p + (size_t)(bk + 16 * i) * NS);

    float2 acc2[8][4];
#pragma unroll
    for (int i = 0; i < 8; i++)
#pragma unroll
        for (int j = 0; j < 4; j++) acc2[i][j] = make_float2(0.f, 0.f);

    int hw = am >> 6;   // which head for ws
    for (int kt = 0; kt < CS; kt += 32) {
        __syncthreads();
        // store prefetched regs to smem (apply decay weight to A)
#pragma unroll
        for (int i = 0; i < 4; i++) {
            int k = ak0 + 4 * i;
            float2 lo = make_float2(xa[i].x * ws[hw][kt + k],     xa[i].y * ws[hw][kt + k + 1]);
            float2 hi = make_float2(xa[i].z * ws[hw][kt + k + 2], xa[i].w * ws[hw][kt + k + 3]);
            *(float2*)&As[am][k]     = lo;
            *(float2*)&As[am][k + 2] = hi;
        }
#pragma unroll
        for (int i = 0; i < 2; i++) {
            Bs[bn4 + 0][bk + 16 * i] = bb[i].x;
            Bs[bn4 + 1][bk + 16 * i] = bb[i].y;
            Bs[bn4 + 2][bk + 16 * i] = bb[i].z;
            Bs[bn4 + 3][bk + 16 * i] = bb[i].w;
        }
        __syncthreads();
        // prefetch next k-tile
        if (kt + 32 < CS) {
            const float4* xp = (const float4*)(g_xt + ((size_t)b * 4096 + m0 + am) * L + c * CS + kt + 32 + ak0);
#pragma unroll
            for (int i = 0; i < 4; i++) xa[i] = xp[i];
#pragma unroll
            for (int i = 0; i < 2; i++)
                bb[i] = *(const float4*)(bm_p + (size_t)(kt + 32 + bk + 16 * i) * NS);
        }
#pragma unroll
        for (int k = 0; k < 32; k += 2) {
            float2 a2[8], b2[4];
#pragma unroll
            for (int i = 0; i < 8; i++) a2[i] = *(const float2*)&As[ty * 8 + i][k];
#pragma unroll
            for (int j = 0; j < 4; j++) b2[j] = *(const float2*)&Bs[tx + 16 * j][k];
#pragma unroll
            for (int i = 0; i < 8; i++)
#pragma unroll
                for (int j = 0; j < 4; j++) acc2[i][j] = fma2(a2[i], b2[j], acc2[i][j]);
        }
    }
    size_t sbase = (size_t)bc * H * P * NS;
#pragma unroll
    for (int i = 0; i < 8; i++)
#pragma unroll
        for (int j = 0; j < 4; j++)
            g_states[sbase + (size_t)(m0 + ty * 8 + i) * NS + nt * 64 + tx + 16 * j] =
                acc2[i][j].x + acc2[i][j].y;
}

// ---------------- K3: state passing across chunks --------------------------
__global__ void k_pass(float* __restrict__ finals) {
    int e = blockIdx.x % 32;
    int h = (blockIdx.x / 32) % H;
    int b = blockIdx.x / (32 * H);
    int pn = e * 256 + threadIdx.x;    // 0..P*NS-1

    size_t cstride = (size_t)H * P * NS;
    size_t base = ((size_t)b * NC * H + h) * P * NS + pn;
    float run = 0.f;
#pragma unroll
    for (int c = 0; c < NC; c++) {
        size_t idx = base + (size_t)c * cstride;
        g_prev[idx] = run;
        run = run * __expf(g_dAl[(b * H + h) * NC + c]) + g_states[idx];
    }
    if (finals) finals[((size_t)(b * H + h)) * P * NS + pn] = run;
}

// ---------------- K4: CB[l,s] = sum_n C[l,n] B[s,n] (per b,c; tril tiles) --
__global__ void __launch_bounds__(256, 2) k_cb(const float* __restrict__ Cm,
                                               const float* __restrict__ Bm) {
    int bc = blockIdx.z;
    int b = bc / NC, c = bc % NC;
    if (blockIdx.x > blockIdx.y) return;  // upper-triangular tiles unused
    int l0 = blockIdx.y * 64, s0 = blockIdx.x * 64;

    __shared__ float Cs[64][34], Bs2[64][34];
    int t = threadIdx.x, ty = t >> 4, tx = t & 15;
    float2 acc2[4][4];
#pragma unroll
    for (int i = 0; i < 4; i++)
#pragma unroll
        for (int j = 0; j < 4; j++) acc2[i][j] = make_float2(0.f, 0.f);

    for (int nt = 0; nt < NS; nt += 32) {
#pragma unroll
        for (int i = 0; i < 8; i++) {
            int e = t + 256 * i;
            int r = e >> 5, k = e & 31;
            Cs[r][k]  = Cm[((size_t)b * L + c * CS + l0 + r) * NS + nt + k];
            Bs2[r][k] = Bm[((size_t)b * L + c * CS + s0 + r) * NS + nt + k];
        }
        __syncthreads();
#pragma unroll
        for (int k = 0; k < 32; k += 2) {
            float2 a2[4], b2[4];
#pragma unroll
            for (int i = 0; i < 4; i++) a2[i] = *(const float2*)&Cs[ty + 16 * i][k];
#pragma unroll
            for (int j = 0; j < 4; j++) b2[j] = *(const float2*)&Bs2[tx + 16 * j][k];
#pragma unroll
            for (int i = 0; i < 4; i++)
#pragma unroll
                for (int j = 0; j < 4; j++) acc2[i][j] = fma2(a2[i], b2[j], acc2[i][j]);
        }
        __syncthreads();
    }
    size_t cb = ((size_t)(b * NC + c)) * CS * CS;
#pragma unroll
    for (int i = 0; i < 4; i++)
#pragma unroll
        for (int j = 0; j < 4; j++)
            g_CB[cb + (size_t)(l0 + ty + 16 * i) * CS + s0 + tx + 16 * j] =
                acc2[i][j].x + acc2[i][j].y;
}

// ---------------- K5: chunk_scan (inter + masked intra + epilogue) --------
// pipelined with register prefetch; x read from g_xt ([p][k] layout native)
__global__ void __launch_bounds__(256, 2) k_scan(const float* __restrict__ x,
                                                 const float* __restrict__ Cm,
                                                 const float* __restrict__ z,
                                                 const float* __restrict__ D,
                                                 float* __restrict__ out) {
    int tmp = blockIdx.x;
    int lt = tmp & 1; tmp >>= 1;
    int h = tmp % H;  tmp /= H;
    int c = tmp % NC;
    int b = tmp / NC;
    int bc = b * NC + c;
    int l0 = lt * 128;

    __shared__ float As[128][34];   // operand A tile [r][k]
    __shared__ float Bs[64][34];    // operand B tile [p][k]
    __shared__ float sdall[CS], sdtall[CS];

    int t = threadIdx.x, ty = t >> 4, tx = t & 15;
    int dbase = ((b * H + h) * NC + c) * CS;
    sdall[t]  = g_dacs[dbase + t];
    sdtall[t] = g_dt[dbase + t];

    float2 acc2[8][4];
#pragma unroll
    for (int i = 0; i < 8; i++)
#pragma unroll
        for (int j = 0; j < 4; j++) acc2[i][j] = make_float2(0.f, 0.f);

    // prefetch mappings (shared by both phases):
    //  A-tile: r = t>>1, k0 = (t&1)*16, 4 x float4
    //  B-tile: p = t>>2, k0 = (t&3)*8,  2 x float4
    int ar = t >> 1, ak0 = (t & 1) * 16;
    int bp = t >> 2, bk0 = (t & 3) * 8;

    // ---------- Phase A: inter-chunk term acc = C[l,:] . prev[p,:], K=128 --
    size_t pbase = (size_t)bc * H * P * NS + (size_t)(h * 64) * NS;
    const float* c_row = Cm + ((size_t)b * L + c * CS + l0 + ar) * NS;
    const float* p_row = g_prev + pbase + (size_t)bp * NS;

    float4 av[4], bv4[2];
#pragma unroll
    for (int i = 0; i < 4; i++) av[i] = *(const float4*)(c_row + ak0 + 4 * i);
#pragma unroll
    for (int i = 0; i < 2; i++) bv4[i] = *(const float4*)(p_row + bk0 + 4 * i);

    for (int nt = 0; nt < 4; nt++) {
        __syncthreads();
#pragma unroll
        for (int i = 0; i < 4; i++) {
            *(float2*)&As[ar][ak0 + 4 * i]     = make_float2(av[i].x, av[i].y);
            *(float2*)&As[ar][ak0 + 4 * i + 2] = make_float2(av[i].z, av[i].w);
        }
#pragma unroll
        for (int i = 0; i < 2; i++) {
            *(float2*)&Bs[bp][bk0 + 4 * i]     = make_float2(bv4[i].x, bv4[i].y);
            *(float2*)&Bs[bp][bk0 + 4 * i + 2] = make_float2(bv4[i].z, bv4[i].w);
        }
        __syncthreads();
        if (nt < 3) {
#pragma unroll
            for (int i = 0; i < 4; i++) av[i] = *(const float4*)(c_row + (nt + 1) * 32 + ak0 + 4 * i);
#pragma unroll
            for (int i = 0; i < 2; i++) bv4[i] = *(const float4*)(p_row + (nt + 1) * 32 + bk0 + 4 * i);
        }
#pragma unroll
        for (int k = 0; k < 32; k += 2) {
            float2 a2[8], b2[4];
#pragma unroll
            for (int i = 0; i < 8; i++) a2[i] = *(const float2*)&As[ty * 8 + i][k];
#pragma unroll
            for (int j = 0; j < 4; j++) b2[j] = *(const float2*)&Bs[tx + 16 * j][k];
#pragma unroll
            for (int i = 0; i < 8; i++)
#pragma unroll
                for (int j = 0; j < 4; j++) acc2[i][j] = fma2(a2[i], b2[j], acc2[i][j]);
        }
    }
    // scale inter term by exp(dA_cumsum[l])
#pragma unroll
    for (int i = 0; i < 8; i++) {
        float el = __expf(sdall[l0 + ty * 8 + i]);
#pragma unroll
        for (int j = 0; j < 4; j++) { acc2[i][j].x *= el; acc2[i][j].y *= el; }
    }

    // ---------- Phase B: intra-chunk masked scores @ x ---------------------
    size_t cbrow = ((size_t)bc) * CS * CS + (size_t)(l0 + ar) * CS;
    const float* xt_row = g_xt + ((size_t)b * 4096 + h * 64 + bp) * L + c * CS;
    float dlr = sdall[l0 + ar];

    int nkt = (lt == 0) ? 4 : 8;
    float4 cb4[4], xv4[2];
#pragma unroll
    for (int i = 0; i < 4; i++) cb4[i] = *(const float4*)(g_CB + cbrow + ak0 + 4 * i);
#pragma unroll
    for (int i = 0; i < 2; i++) xv4[i] = *(const float4*)(xt_row + bk0 + 4 * i);

    for (int kt = 0; kt < nkt; kt++) {
        int s0 = kt * 32;
        __syncthreads();
        // construct score tile from prefetched CB
#pragma unroll
        for (int i = 0; i < 4; i++) {
            int k = ak0 + 4 * i;
            float vq[4] = {cb4[i].x, cb4[i].y, cb4[i].z, cb4[i].w};
            float2 lo, hi;
#pragma unroll
            for (int q = 0; q < 4; q++) {
                int s = s0 + k + q;
                float v = 0.f;
                if (s <= l0 + ar)
                    v = vq[q] * __expf(dlr - sdall[s]) * sdtall[s];
                vq[q] = v;
            }
            lo = make_float2(vq[0], vq[1]);
            hi = make_float2(vq[2], vq[3]);
            *(float2*)&As[ar][k]     = lo;
            *(float2*)&As[ar][k + 2] = hi;
        }
#pragma unroll
        for (int i = 0; i < 2; i++) {
            *(float2*)&Bs[bp][bk0 + 4 * i]     = make_float2(xv4[i].x, xv4[i].y);
            *(float2*)&Bs[bp][bk0 + 4 * i + 2] = make_float2(xv4[i].z, xv4[i].w);
        }
        __syncthreads();
        if (kt + 1 < nkt) {
#pragma unroll
            for (int i = 0; i < 4; i++)
                cb4[i] = *(const float4*)(g_CB + cbrow + (s0 + 32) + ak0 + 4 * i);
#pragma unroll
            for (int i = 0; i < 2; i++)
                xv4[i] = *(const float4*)(xt_row + (s0 + 32) + bk0 + 4 * i);
        }
#pragma unroll
        for (int k = 0; k < 32; k += 2) {
            float2 a2[8], b2[4];
#pragma unroll
            for (int i = 0; i < 8; i++) a2[i] = *(const float2*)&As[ty * 8 + i][k];
#pragma unroll
            for (int j = 0; j < 4; j++) b2[j] = *(const float2*)&Bs[tx + 16 * j][k];
#pragma unroll
            for (int i = 0; i < 8; i++)
#pragma unroll
                for (int j = 0; j < 4; j++) acc2[i][j] = fma2(a2[i], b2[j], acc2[i][j]);
        }
    }

    // Epilogue: fold k-parity, + x*D, * silu(z)
    float Dh = D[h];
#pragma unroll
    for (int i = 0; i < 8; i++) {
#pragma unroll
        for (int j = 0; j < 4; j++) {
            int l = l0 + ty * 8 + i, p = tx + 16 * j;
            size_t gi = (((size_t)b * L + c * CS + l) * H + h) * P + p;
            float xv = x[gi], zv = z[gi];
            float o = acc2[i][j].x + acc2[i][j].y + xv * Dh;
            float sil = zv / (1.f + __expf(-zv));
            out[gi] = o * sil;
        }
    }
}

// ---------------- launch ----------------------------------------------------
extern "C" void kernel_launch(void* const* d_in, const int* in_sizes, int n_in,
                              void* d_out, int out_size) {
    const float* x   = (const float*)d_in[0];
    const float* dt  = (const float*)d_in[1];
    const float* A   = (const float*)d_in[2];
    const float* Bm  = (const float*)d_in[3];
    const float* Cm  = (const float*)d_in[4];
    const float* D   = (const float*)d_in[5];
    const float* z   = (const float*)d_in[6];
    const float* dtb = (const float*)d_in[7];
    (void)in_sizes; (void)n_in;

    float* out = (float*)d_out;
    const int OUT_ELEMS = Bb * L * H * P;            // 16777216
    const int FIN_ELEMS = Bb * H * P * NS;           // 1048576
    float* finals = (out_size >= OUT_ELEMS + FIN_ELEMS) ? (out + OUT_ELEMS) : nullptr;

    k_dt    <<<Bb * H * NC, CS>>>(dt, A, dtb);
    dim3 gx(128, 8, Bb * NC);
    k_xt    <<<gx, dim3(32, 8)>>>(x);
    k_state2<<<Bb * NC * 32 * 2, 256>>>(Bm);
    k_pass  <<<Bb * H * 32, 256>>>(finals);
    dim3 g4(4, 4, Bb * NC);
    k_cb    <<<g4, 256>>>(Cm, Bm);
    k_scan  <<<Bb * NC * H * 2, 256>>>(x, Cm, z, D, out);
}

// round 8
// speedup vs baseline: 1.3027x; 1.3027x over previous
#include <cuda_runtime.h>
#include <math.h>
#include <stdint.h>

// Fixed problem shape (from setup_inputs)
#define Bb 2
#define L  2048
#define H  64
#define P  64
#define NS 128
#define CS 256
#define NC 8
#define LOG2E 1.4426950408889634f

// ---------------- scratch (static device globals; no runtime alloc) -------
__device__ float g_dt   [Bb*H*NC*CS];            // softplus(dt+bias)
__device__ float g_dacs [Bb*H*NC*CS];            // cumsum(dA) within chunk
__device__ float g_dAl  [Bb*H*NC];               // last cumsum per chunk
__device__ float g_states[(size_t)Bb*NC*H*P*NS]; // chunk end-state contribs
__device__ float g_prev  [(size_t)Bb*NC*H*P*NS]; // propagated prev states
__device__ float g_CB   [(size_t)Bb*NC*CS*CS];   // C @ B^T per (b,c)
__device__ float g_xw1  [(size_t)Bb*H*P*L];      // x*exp(dAl-dacs)*dt  [b,(h,p),l]
__device__ float g_xw2  [(size_t)Bb*H*P*L];      // x*dt                [b,(h,p),l]
__device__ float g_Bt   [(size_t)Bb*NS*L];       // B^T                 [b,n,l]

// packed dual-FMA: one FFMA2 instruction
__device__ __forceinline__ float2 fma2(float2 a, float2 b, float2 c) {
    unsigned long long ua = *reinterpret_cast<unsigned long long*>(&a);
    unsigned long long ub = *reinterpret_cast<unsigned long long*>(&b);
    unsigned long long uc = *reinterpret_cast<unsigned long long*>(&c);
    asm("fma.rn.f32x2 %0, %1, %2, %0;" : "+l"(uc) : "l"(ua), "l"(ub));
    return *reinterpret_cast<float2*>(&uc);
}
__device__ __forceinline__ float ex2(float x) {
    float y; asm("ex2.approx.ftz.f32 %0, %1;" : "=f"(y) : "f"(x)); return y;
}
__device__ __forceinline__ void cpa16(void* s, const void* g) {
    uint32_t sa = (uint32_t)__cvta_generic_to_shared(s);
    asm volatile("cp.async.ca.shared.global [%0], [%1], 16;" :: "r"(sa), "l"(g) : "memory");
}
#define CP_COMMIT() asm volatile("cp.async.commit_group;" ::: "memory")
#define CP_WAIT1()  asm volatile("cp.async.wait_group 1;" ::: "memory")
#define CP_WAIT0()  asm volatile("cp.async.wait_group 0;" ::: "memory")

#define SMEM_ST ((2*128*36 + 2*64*36) * 4)
#define SMEM_SC ((2*128*36 + 2*64*36 + 512) * 4)

// ---------------- K1: dt softplus + per-chunk cumsum ----------------------
__global__ void k_dt(const float* __restrict__ dt, const float* __restrict__ A,
                     const float* __restrict__ dtb) {
    int idx = blockIdx.x;
    int c = idx % NC;
    int h = (idx / NC) % H;
    int b = idx / (NC * H);
    int s = threadIdx.x;
    int lg = c * CS + s;

    float v = dt[((size_t)b * L + lg) * H + h] + dtb[h];
    float sp = (v > 20.f) ? v : log1pf(__expf(v));
    float dA = sp * A[h];

    __shared__ float sm[CS];
    sm[s] = dA;
    __syncthreads();
#pragma unroll
    for (int off = 1; off < CS; off <<= 1) {
        float pv = (s >= off) ? sm[s - off] : 0.f;
        __syncthreads();
        sm[s] += pv;
        __syncthreads();
    }
    int base = ((b * H + h) * NC + c) * CS;
    g_dt[base + s] = sp;
    g_dacs[base + s] = sm[s];
    if (s == CS - 1) g_dAl[(b * H + h) * NC + c] = sm[s];
}

// ---------------- K1b: weighted transposes of x ----------------------------
__global__ void k_xw(const float* __restrict__ x) {
    __shared__ float tile[32][33];
    int bc = blockIdx.z;
    int b = bc >> 3, c = bc & 7;
    int m0 = blockIdx.x * 32, s0 = blockIdx.y * 32;
    int tx = threadIdx.x, ty = threadIdx.y;   // 32 x 8
#pragma unroll
    for (int j = 0; j < 4; j++)
        tile[ty + 8 * j][tx] = x[((size_t)(b * L + c * CS + s0 + ty + 8 * j)) * 4096 + m0 + tx];

    int h = m0 >> 6;
    int dbase = ((b * H + h) * NC + c) * CS;
    float dlast = g_dAl[(b * H + h) * NC + c];
    float dtv = g_dt[dbase + s0 + tx];
    float w1 = ex2((dlast - g_dacs[dbase + s0 + tx]) * LOG2E) * dtv;
    __syncthreads();
#pragma unroll
    for (int j = 0; j < 4; j++) {
        float v = tile[tx][ty + 8 * j];
        size_t o = ((size_t)b * 4096 + m0 + ty + 8 * j) * L + c * CS + s0 + tx;
        g_xw1[o] = v * w1;
        g_xw2[o] = v * dtv;
    }
}

// ---------------- K1c: B transpose -> g_Bt[b,n,l] --------------------------
__global__ void k_Bt(const float* __restrict__ Bm) {
    __shared__ float tile[32][33];
    int bc = blockIdx.z;
    int b = bc >> 3, c = bc & 7;
    int n0 = blockIdx.x * 32, s0 = blockIdx.y * 32;
    int tx = threadIdx.x, ty = threadIdx.y;
#pragma unroll
    for (int j = 0; j < 4; j++)
        tile[ty + 8 * j][tx] = Bm[((size_t)(b * L + c * CS + s0 + ty + 8 * j)) * NS + n0 + tx];
    __syncthreads();
#pragma unroll
    for (int j = 0; j < 4; j++)
        g_Bt[((size_t)b * NS + n0 + ty + 8 * j) * L + c * CS + s0 + tx] = tile[tx][ty + 8 * j];
}

// ---------------- K2: chunk_state, cp.async double-buffered GEMM ----------
// states[(h,p), n] = sum_s xw1[(h,p), s] * Bt[n, s]   M=4096 N=128 K=256
__global__ void __launch_bounds__(256, 2) k_state2() {
    extern __shared__ __align__(16) float smp[];
    float (*As)[128][36] = (float(*)[128][36])smp;
    float (*Bs)[64][36]  = (float(*)[64][36])(smp + 2 * 128 * 36);

    int blk = blockIdx.x;
    int nt = blk & 1; blk >>= 1;
    int mt = blk & 31; blk >>= 5;
    int bc = blk;
    int b = bc >> 3, c = bc & 7;
    int m0 = mt * 128, n0 = nt * 64;

    int t = threadIdx.x, ty = t >> 4, tx = t & 15;
    int arow = t >> 3, akc4 = (t & 7) * 4;

    const float* a_base = g_xw1 + ((size_t)b * 4096 + m0) * L + c * CS;
    const float* b_base = g_Bt + ((size_t)b * NS + n0) * L + c * CS;

    // preload tile 0
#pragma unroll
    for (int i = 0; i < 4; i++)
        cpa16(&As[0][arow + 32 * i][akc4], a_base + (size_t)(arow + 32 * i) * L + akc4);
#pragma unroll
    for (int i = 0; i < 2; i++)
        cpa16(&Bs[0][arow + 32 * i][akc4], b_base + (size_t)(arow + 32 * i) * L + akc4);
    CP_COMMIT();

    float2 acc2[8][4];
#pragma unroll
    for (int i = 0; i < 8; i++)
#pragma unroll
        for (int j = 0; j < 4; j++) acc2[i][j] = make_float2(0.f, 0.f);

    for (int kt = 0; kt < 8; kt++) {
        int cur = kt & 1;
        if (kt + 1 < 8) {
            int nb = cur ^ 1, off = (kt + 1) * 32;
#pragma unroll
            for (int i = 0; i < 4; i++)
                cpa16(&As[nb][arow + 32 * i][akc4], a_base + (size_t)(arow + 32 * i) * L + off + akc4);
#pragma unroll
            for (int i = 0; i < 2; i++)
                cpa16(&Bs[nb][arow + 32 * i][akc4], b_base + (size_t)(arow + 32 * i) * L + off + akc4);
            CP_COMMIT();
            CP_WAIT1();
        } else {
            CP_WAIT0();
        }
        __syncthreads();
#pragma unroll
        for (int k = 0; k < 32; k += 2) {
            float2 a2[8], b2[4];
#pragma unroll
            for (int i = 0; i < 8; i++) a2[i] = *(const float2*)&As[cur][ty * 8 + i][k];
#pragma unroll
            for (int j = 0; j < 4; j++) b2[j] = *(const float2*)&Bs[cur][tx + 16 * j][k];
#pragma unroll
            for (int i = 0; i < 8; i++)
#pragma unroll
                for (int j = 0; j < 4; j++) acc2[i][j] = fma2(a2[i], b2[j], acc2[i][j]);
        }
        __syncthreads();
    }
    size_t sbase = (size_t)bc * H * P * NS;
#pragma unroll
    for (int i = 0; i < 8; i++)
#pragma unroll
        for (int j = 0; j < 4; j++)
            g_states[sbase + (size_t)(m0 + ty * 8 + i) * NS + n0 + tx + 16 * j] =
                acc2[i][j].x + acc2[i][j].y;
}

// ---------------- K3: state passing across chunks --------------------------
__global__ void k_pass(float* __restrict__ finals) {
    int e = blockIdx.x % 32;
    int h = (blockIdx.x / 32) % H;
    int b = blockIdx.x / (32 * H);
    int pn = e * 256 + threadIdx.x;

    size_t cstride = (size_t)H * P * NS;
    size_t base = ((size_t)b * NC * H + h) * P * NS + pn;
    float run = 0.f;
#pragma unroll
    for (int c = 0; c < NC; c++) {
        size_t idx = base + (size_t)c * cstride;
        g_prev[idx] = run;
        run = run * __expf(g_dAl[(b * H + h) * NC + c]) + g_states[idx];
    }
    if (finals) finals[((size_t)(b * H + h)) * P * NS + pn] = run;
}

// ---------------- K4: CB[l,s] = sum_n C[l,n] B[s,n], tril tiles only -------
__global__ void __launch_bounds__(256, 2) k_cb(const float* __restrict__ Cm,
                                               const float* __restrict__ Bm) {
    __shared__ __align__(16) float Cs[2][64][36];
    __shared__ __align__(16) float Bs2[2][64][36];
    const int LY[10] = {0,1,1,2,2,2,3,3,3,3};
    const int SX[10] = {0,0,1,0,1,2,0,1,2,3};

    int bc = blockIdx.x / 10;
    int ti = blockIdx.x % 10;
    int b = bc >> 3, c = bc & 7;
    int l0 = LY[ti] * 64, s0 = SX[ti] * 64;

    int t = threadIdx.x, ty = t >> 4, tx = t & 15;
    int arow = t >> 3, akc4 = (t & 7) * 4;

    const float* c_base = Cm + (size_t)(b * L + c * CS + l0) * NS;
    const float* b_base = Bm + (size_t)(b * L + c * CS + s0) * NS;

#pragma unroll
    for (int i = 0; i < 2; i++) {
        cpa16(&Cs[0][arow + 32 * i][akc4],  c_base + (size_t)(arow + 32 * i) * NS + akc4);
        cpa16(&Bs2[0][arow + 32 * i][akc4], b_base + (size_t)(arow + 32 * i) * NS + akc4);
    }
    CP_COMMIT();

    float2 acc2[4][4];
#pragma unroll
    for (int i = 0; i < 4; i++)
#pragma unroll
        for (int j = 0; j < 4; j++) acc2[i][j] = make_float2(0.f, 0.f);

    for (int kt = 0; kt < 4; kt++) {
        int cur = kt & 1;
        if (kt + 1 < 4) {
            int nb = cur ^ 1, off = (kt + 1) * 32;
#pragma unroll
            for (int i = 0; i < 2; i++) {
                cpa16(&Cs[nb][arow + 32 * i][akc4],  c_base + (size_t)(arow + 32 * i) * NS + off + akc4);
                cpa16(&Bs2[nb][arow + 32 * i][akc4], b_base + (size_t)(arow + 32 * i) * NS + off + akc4);
            }
            CP_COMMIT();
            CP_WAIT1();
        } else {
            CP_WAIT0();
        }
        __syncthreads();
#pragma unroll
        for (int k = 0; k < 32; k += 2) {
            float2 a2[4], b2[4];
#pragma unroll
            for (int i = 0; i < 4; i++) a2[i] = *(const float2*)&Cs[cur][ty + 16 * i][k];
#pragma unroll
            for (int j = 0; j < 4; j++) b2[j] = *(const float2*)&Bs2[cur][tx + 16 * j][k];
#pragma unroll
            for (int i = 0; i < 4; i++)
#pragma unroll
                for (int j = 0; j < 4; j++) acc2[i][j] = fma2(a2[i], b2[j], acc2[i][j]);
        }
        __syncthreads();
    }
    size_t cb = ((size_t)bc) * CS * CS;
#pragma unroll
    for (int i = 0; i < 4; i++)
#pragma unroll
        for (int j = 0; j < 4; j++)
            g_CB[cb + (size_t)(l0 + ty + 16 * i) * CS + s0 + tx + 16 * j] =
                acc2[i][j].x + acc2[i][j].y;
}

// ---------------- K5: chunk_scan (inter + masked intra + epilogue) --------
__global__ void __launch_bounds__(256, 2) k_scan(const float* __restrict__ x,
                                                 const float* __restrict__ Cm,
                                                 const float* __restrict__ z,
                                                 const float* __restrict__ D,
                                                 float* __restrict__ out) {
    extern __shared__ __align__(16) float smp[];
    float (*As)[128][36] = (float(*)[128][36])smp;
    float (*Bs)[64][36]  = (float(*)[64][36])(smp + 2 * 128 * 36);
    float* sdall = smp + 2 * 128 * 36 + 2 * 64 * 36;   // 256
    float* sd2   = sdall + 256;                        // 256

    int tmp = blockIdx.x;
    int lt = tmp & 1; tmp >>= 1;
    int h = tmp % H;  tmp /= H;
    int c = tmp % NC;
    int b = tmp / NC;
    int bc = b * NC + c;
    int l0 = lt * 128;

    int t = threadIdx.x, ty = t >> 4, tx = t & 15;
    int dbase = ((b * H + h) * NC + c) * CS;
    float dv = g_dacs[dbase + t];
    sdall[t] = dv;
    sd2[t] = dv * LOG2E;

    int arow = t >> 3, akc4 = (t & 7) * 4;

    // ---------- Phase A: acc = C[l,:] . prev[(h,p),:], K = 128 -------------
    const float* c_base = Cm + (size_t)(b * L + c * CS + l0) * NS;
    const float* p_base = g_prev + (size_t)bc * H * P * NS + (size_t)(h * 64) * NS;

#pragma unroll
    for (int i = 0; i < 4; i++)
        cpa16(&As[0][arow + 32 * i][akc4], c_base + (size_t)(arow + 32 * i) * NS + akc4);
#pragma unroll
    for (int i = 0; i < 2; i++)
        cpa16(&Bs[0][arow + 32 * i][akc4], p_base + (size_t)(arow + 32 * i) * NS + akc4);
    CP_COMMIT();

    float2 acc2[8][4];
#pragma unroll
    for (int i = 0; i < 8; i++)
#pragma unroll
        for (int j = 0; j < 4; j++) acc2[i][j] = make_float2(0.f, 0.f);

    for (int kt = 0; kt < 4; kt++) {
        int cur = kt & 1;
        if (kt + 1 < 4) {
            int nb = cur ^ 1, off = (kt + 1) * 32;
#pragma unroll
            for (int i = 0; i < 4; i++)
                cpa16(&As[nb][arow + 32 * i][akc4], c_base + (size_t)(arow + 32 * i) * NS + off + akc4);
#pragma unroll
            for (int i = 0; i < 2; i++)
                cpa16(&Bs[nb][arow + 32 * i][akc4], p_base + (size_t)(arow + 32 * i) * NS + off + akc4);
            CP_COMMIT();
            CP_WAIT1();
        } else {
            CP_WAIT0();
        }
        __syncthreads();
#pragma unroll
        for (int k = 0; k < 32; k += 2) {
            float2 a2[8], b2[4];
#pragma unroll
            for (int i = 0; i < 8; i++) a2[i] = *(const float2*)&As[cur][ty * 8 + i][k];
#pragma unroll
            for (int j = 0; j < 4; j++) b2[j] = *(const float2*)&Bs[cur][tx + 16 * j][k];
#pragma unroll
            for (int i = 0; i < 8; i++)
#pragma unroll
                for (int j = 0; j < 4; j++) acc2[i][j] = fma2(a2[i], b2[j], acc2[i][j]);
        }
        __syncthreads();
    }
    // scale inter term by exp(dacs[l]) = ex2(sd2[l])
#pragma unroll
    for (int i = 0; i < 8; i++) {
        float el = ex2(sd2[l0 + ty * 8 + i]);
#pragma unroll
        for (int j = 0; j < 4; j++) { acc2[i][j].x *= el; acc2[i][j].y *= el; }
    }

    // ---------- Phase B: masked intra scores @ (x*dt), K = s ---------------
    const float* cb_base = g_CB + (size_t)bc * CS * CS + (size_t)l0 * CS;
    const float* x_base  = g_xw2 + ((size_t)b * 4096 + h * 64) * L + c * CS;
    int nkt = (lt == 0) ? 4 : 8;
    int tr = t >> 1, tk0 = (t & 1) * 16;
    int lr = l0 + tr;
    float dlr2 = sd2[lr];

#pragma unroll
    for (int i = 0; i < 4; i++)
        cpa16(&As[0][arow + 32 * i][akc4], cb_base + (size_t)(arow + 32 * i) * CS + akc4);
#pragma unroll
    for (int i = 0; i < 2; i++)
        cpa16(&Bs[0][arow + 32 * i][akc4], x_base + (size_t)(arow + 32 * i) * L + akc4);
    CP_COMMIT();

    for (int kt = 0; kt < nkt; kt++) {
        int cur = kt & 1;
        int s0 = kt * 32;
        if (kt + 1 < nkt) {
            int nb = cur ^ 1, off = s0 + 32;
#pragma unroll
            for (int i = 0; i < 4; i++)
                cpa16(&As[nb][arow + 32 * i][akc4], cb_base + (size_t)(arow + 32 * i) * CS + off + akc4);
#pragma unroll
            for (int i = 0; i < 2; i++)
                cpa16(&Bs[nb][arow + 32 * i][akc4], x_base + (size_t)(arow + 32 * i) * L + off + akc4);
            CP_COMMIT();
            CP_WAIT1();
        } else {
            CP_WAIT0();
        }
        __syncthreads();
        // transform raw CB tile in place: v *= exp(dacs[l]-dacs[s]); mask s>l
#pragma unroll
        for (int i = 0; i < 4; i++) {
            int k = tk0 + 4 * i;
            int s = s0 + k;
            float4 v = *(float4*)&As[cur][tr][k];
            v.x = (s     <= lr) ? v.x * ex2(dlr2 - sd2[s])     : 0.f;
            v.y = (s + 1 <= lr) ? v.y * ex2(dlr2 - sd2[s + 1]) : 0.f;
            v.z = (s + 2 <= lr) ? v.z * ex2(dlr2 - sd2[s + 2]) : 0.f;
            v.w = (s + 3 <= lr) ? v.w * ex2(dlr2 - sd2[s + 3]) : 0.f;
            *(float4*)&As[cur][tr][k] = v;
        }
        __syncthreads();
#pragma unroll
        for (int k = 0; k < 32; k += 2) {
            float2 a2[8], b2[4];
#pragma unroll
            for (int i = 0; i < 8; i++) a2[i] = *(const float2*)&As[cur][ty * 8 + i][k];
#pragma unroll
            for (int j = 0; j < 4; j++) b2[j] = *(const float2*)&Bs[cur][tx + 16 * j][k];
#pragma unroll
            for (int i = 0; i < 8; i++)
#pragma unroll
                for (int j = 0; j < 4; j++) acc2[i][j] = fma2(a2[i], b2[j], acc2[i][j]);
        }
        __syncthreads();
    }

    // Epilogue: fold k-parity, + x*D, * silu(z)
    float Dh = D[h];
#pragma unroll
    for (int i = 0; i < 8; i++) {
#pragma unroll
        for (int j = 0; j < 4; j++) {
            int l = l0 + ty * 8 + i, p = tx + 16 * j;
            size_t gi = (((size_t)b * L + c * CS + l) * H + h) * P + p;
            float xv = x[gi], zv = z[gi];
            float o = acc2[i][j].x + acc2[i][j].y + xv * Dh;
            float sil = zv / (1.f + __expf(-zv));
            out[gi] = o * sil;
        }
    }
}

// ---------------- launch ----------------------------------------------------
extern "C" void kernel_launch(void* const* d_in, const int* in_sizes, int n_in,
                              void* d_out, int out_size) {
    const float* x   = (const float*)d_in[0];
    const float* dt  = (const float*)d_in[1];
    const float* A   = (const float*)d_in[2];
    const float* Bm  = (const float*)d_in[3];
    const float* Cm  = (const float*)d_in[4];
    const float* D   = (const float*)d_in[5];
    const float* z   = (const float*)d_in[6];
    const float* dtb = (const float*)d_in[7];
    (void)in_sizes; (void)n_in;

    float* out = (float*)d_out;
    const int OUT_ELEMS = Bb * L * H * P;
    const int FIN_ELEMS = Bb * H * P * NS;
    float* finals = (out_size >= OUT_ELEMS + FIN_ELEMS) ? (out + OUT_ELEMS) : nullptr;

    static int attr_done = 0;
    if (!attr_done) {
        cudaFuncSetAttribute(k_state2, cudaFuncAttributeMaxDynamicSharedMemorySize, SMEM_ST);
        cudaFuncSetAttribute(k_scan,   cudaFuncAttributeMaxDynamicSharedMemorySize, SMEM_SC);
        attr_done = 1;
    }

    k_dt    <<<Bb * H * NC, CS>>>(dt, A, dtb);
    dim3 gxw(128, 8, Bb * NC);
    k_xw    <<<gxw, dim3(32, 8)>>>(x);
    dim3 gbt(4, 8, Bb * NC);
    k_Bt    <<<gbt, dim3(32, 8)>>>(Bm);
    k_state2<<<Bb * NC * 32 * 2, 256, SMEM_ST>>>();
    k_pass  <<<Bb * H * 32, 256>>>(finals);
    k_cb    <<<Bb * NC * 10, 256>>>(Cm, Bm);
    k_scan  <<<Bb * NC * H * 2, 256, SMEM_SC>>>(x, Cm, z, D, out);
}

// round 9
// speedup vs baseline: 1.3043x; 1.0012x over previous
#include <cuda_runtime.h>
#include <math.h>
#include <stdint.h>

// Fixed problem shape (from setup_inputs)
#define Bb 2
#define L  2048
#define H  64
#define P  64
#define NS 128
#define CS 256
#define NC 8
#define LOG2E 1.4426950408889634f

// ---------------- scratch (static device globals; no runtime alloc) -------
__device__ float g_dt   [Bb*H*NC*CS];            // softplus(dt+bias)
__device__ float g_dacs [Bb*H*NC*CS];            // cumsum(dA) within chunk
__device__ float g_dAl  [Bb*H*NC];               // last cumsum per chunk
__device__ float g_states[(size_t)Bb*NC*H*P*NS]; // chunk end-state contribs
__device__ float g_prev  [(size_t)Bb*NC*H*P*NS]; // propagated prev states
__device__ float g_CB   [(size_t)Bb*NC*CS*CS];   // C @ B^T per (b,c)
__device__ float g_xw1  [(size_t)Bb*H*P*L];      // x*exp(dAl-dacs)*dt  [b,(h,p),l]
__device__ float g_xw2  [(size_t)Bb*H*P*L];      // x*dt                [b,(h,p),l]
__device__ float g_Bt   [(size_t)Bb*NS*L];       // B^T                 [b,n,l]

// packed dual-FMA: one FFMA2 instruction
__device__ __forceinline__ float2 fma2(float2 a, float2 b, float2 c) {
    unsigned long long ua = *reinterpret_cast<unsigned long long*>(&a);
    unsigned long long ub = *reinterpret_cast<unsigned long long*>(&b);
    unsigned long long uc = *reinterpret_cast<unsigned long long*>(&c);
    asm("fma.rn.f32x2 %0, %1, %2, %0;" : "+l"(uc) : "l"(ua), "l"(ub));
    return *reinterpret_cast<float2*>(&uc);
}
__device__ __forceinline__ float ex2(float x) {
    float y; asm("ex2.approx.ftz.f32 %0, %1;" : "=f"(y) : "f"(x)); return y;
}
__device__ __forceinline__ void cpa16(void* s, const void* g) {
    uint32_t sa = (uint32_t)__cvta_generic_to_shared(s);
    asm volatile("cp.async.ca.shared.global [%0], [%1], 16;" :: "r"(sa), "l"(g) : "memory");
}
#define CP_COMMIT() asm volatile("cp.async.commit_group;" ::: "memory")
#define CP_WAIT1()  asm volatile("cp.async.wait_group 1;" ::: "memory")
#define CP_WAIT0()  asm volatile("cp.async.wait_group 0;" ::: "memory")

#define SMEM_ST ((2*128*36 + 2*64*36) * 4)
#define SMEM_SC ((2*128*36 + 2*64*36 + 512) * 4)

// ---------------- K1: dt softplus + per-chunk cumsum ----------------------
__global__ void k_dt(const float* __restrict__ dt, const float* __restrict__ A,
                     const float* __restrict__ dtb) {
    int idx = blockIdx.x;
    int c = idx % NC;
    int h = (idx / NC) % H;
    int b = idx / (NC * H);
    int s = threadIdx.x;
    int lg = c * CS + s;

    float v = dt[((size_t)b * L + lg) * H + h] + dtb[h];
    float sp = (v > 20.f) ? v : log1pf(__expf(v));
    float dA = sp * A[h];

    __shared__ float sm[CS];
    sm[s] = dA;
    __syncthreads();
#pragma unroll
    for (int off = 1; off < CS; off <<= 1) {
        float pv = (s >= off) ? sm[s - off] : 0.f;
        __syncthreads();
        sm[s] += pv;
        __syncthreads();
    }
    int base = ((b * H + h) * NC + c) * CS;
    g_dt[base + s] = sp;
    g_dacs[base + s] = sm[s];
    if (s == CS - 1) g_dAl[(b * H + h) * NC + c] = sm[s];
}

// ---------------- K1b: weighted transposes of x ----------------------------
__global__ void k_xw(const float* __restrict__ x) {
    __shared__ float tile[32][33];
    int bc = blockIdx.z;
    int b = bc >> 3, c = bc & 7;
    int m0 = blockIdx.x * 32, s0 = blockIdx.y * 32;
    int tx = threadIdx.x, ty = threadIdx.y;   // 32 x 8
#pragma unroll
    for (int j = 0; j < 4; j++)
        tile[ty + 8 * j][tx] = x[((size_t)(b * L + c * CS + s0 + ty + 8 * j)) * 4096 + m0 + tx];

    int h = m0 >> 6;
    int dbase = ((b * H + h) * NC + c) * CS;
    float dlast = g_dAl[(b * H + h) * NC + c];
    float dtv = g_dt[dbase + s0 + tx];
    float w1 = ex2((dlast - g_dacs[dbase + s0 + tx]) * LOG2E) * dtv;
    __syncthreads();
#pragma unroll
    for (int j = 0; j < 4; j++) {
        float v = tile[tx][ty + 8 * j];
        size_t o = ((size_t)b * 4096 + m0 + ty + 8 * j) * L + c * CS + s0 + tx;
        g_xw1[o] = v * w1;
        g_xw2[o] = v * dtv;
    }
}

// ---------------- K1c: B transpose -> g_Bt[b,n,l] --------------------------
__global__ void k_Bt(const float* __restrict__ Bm) {
    __shared__ float tile[32][33];
    int bc = blockIdx.z;
    int b = bc >> 3, c = bc & 7;
    int n0 = blockIdx.x * 32, s0 = blockIdx.y * 32;
    int tx = threadIdx.x, ty = threadIdx.y;
#pragma unroll
    for (int j = 0; j < 4; j++)
        tile[ty + 8 * j][tx] = Bm[((size_t)(b * L + c * CS + s0 + ty + 8 * j)) * NS + n0 + tx];
    __syncthreads();
#pragma unroll
    for (int j = 0; j < 4; j++)
        g_Bt[((size_t)b * NS + n0 + ty + 8 * j) * L + c * CS + s0 + tx] = tile[tx][ty + 8 * j];
}

// ---------------- K2: chunk_state, cp.async double-buffered GEMM ----------
// states[(h,p), n] = sum_s xw1[(h,p), s] * Bt[n, s]   M=4096 N=128 K=256
__global__ void __launch_bounds__(256, 2) k_state2() {
    extern __shared__ __align__(16) float smp[];
    float (*As)[128][36] = (float(*)[128][36])smp;
    float (*Bs)[64][36]  = (float(*)[64][36])(smp + 2 * 128 * 36);

    int blk = blockIdx.x;
    int nt = blk & 1; blk >>= 1;
    int mt = blk & 31; blk >>= 5;
    int bc = blk;
    int b = bc >> 3, c = bc & 7;
    int m0 = mt * 128, n0 = nt * 64;

    int t = threadIdx.x, ty = t >> 4, tx = t & 15;
    int arow = t >> 3, akc4 = (t & 7) * 4;

    const float* a_base = g_xw1 + ((size_t)b * 4096 + m0) * L + c * CS;
    const float* b_base = g_Bt + ((size_t)b * NS + n0) * L + c * CS;

    // preload tile 0
#pragma unroll
    for (int i = 0; i < 4; i++)
        cpa16(&As[0][arow + 32 * i][akc4], a_base + (size_t)(arow + 32 * i) * L + akc4);
#pragma unroll
    for (int i = 0; i < 2; i++)
        cpa16(&Bs[0][arow + 32 * i][akc4], b_base + (size_t)(arow + 32 * i) * L + akc4);
    CP_COMMIT();

    float2 acc2[8][4];
#pragma unroll
    for (int i = 0; i < 8; i++)
#pragma unroll
        for (int j = 0; j < 4; j++) acc2[i][j] = make_float2(0.f, 0.f);

    for (int kt = 0; kt < 8; kt++) {
        int cur = kt & 1;
        if (kt + 1 < 8) {
            int nb = cur ^ 1, off = (kt + 1) * 32;
#pragma unroll
            for (int i = 0; i < 4; i++)
                cpa16(&As[nb][arow + 32 * i][akc4], a_base + (size_t)(arow + 32 * i) * L + off + akc4);
#pragma unroll
            for (int i = 0; i < 2; i++)
                cpa16(&Bs[nb][arow + 32 * i][akc4], b_base + (size_t)(arow + 32 * i) * L + off + akc4);
            CP_COMMIT();
            CP_WAIT1();
        } else {
            CP_WAIT0();
        }
        __syncthreads();
#pragma unroll
        for (int k = 0; k < 32; k += 2) {
            float2 a2[8], b2[4];
#pragma unroll
            for (int i = 0; i < 8; i++) a2[i] = *(const float2*)&As[cur][ty * 8 + i][k];
#pragma unroll
            for (int j = 0; j < 4; j++) b2[j] = *(const float2*)&Bs[cur][tx + 16 * j][k];
#pragma unroll
            for (int i = 0; i < 8; i++)
#pragma unroll
                for (int j = 0; j < 4; j++) acc2[i][j] = fma2(a2[i], b2[j], acc2[i][j]);
        }
        __syncthreads();
    }
    size_t sbase = (size_t)bc * H * P * NS;
#pragma unroll
    for (int i = 0; i < 8; i++)
#pragma unroll
        for (int j = 0; j < 4; j++)
            g_states[sbase + (size_t)(m0 + ty * 8 + i) * NS + n0 + tx + 16 * j] =
                acc2[i][j].x + acc2[i][j].y;
}

// ---------------- K3: state passing across chunks --------------------------
__global__ void k_pass(float* __restrict__ finals) {
    int e = blockIdx.x % 32;
    int h = (blockIdx.x / 32) % H;
    int b = blockIdx.x / (32 * H);
    int pn = e * 256 + threadIdx.x;

    size_t cstride = (size_t)H * P * NS;
    size_t base = ((size_t)b * NC * H + h) * P * NS + pn;
    float run = 0.f;
#pragma unroll
    for (int c = 0; c < NC; c++) {
        size_t idx = base + (size_t)c * cstride;
        g_prev[idx] = run;
        run = run * __expf(g_dAl[(b * H + h) * NC + c]) + g_states[idx];
    }
    if (finals) finals[((size_t)(b * H + h)) * P * NS + pn] = run;
}

// ---------------- K4: CB[l,s] = sum_n C[l,n] B[s,n], tril tiles only -------
__global__ void __launch_bounds__(256, 2) k_cb(const float* __restrict__ Cm,
                                               const float* __restrict__ Bm) {
    __shared__ __align__(16) float Cs[2][64][36];
    __shared__ __align__(16) float Bs2[2][64][36];
    const int LY[10] = {0,1,1,2,2,2,3,3,3,3};
    const int SX[10] = {0,0,1,0,1,2,0,1,2,3};

    int bc = blockIdx.x / 10;
    int ti = blockIdx.x % 10;
    int b = bc >> 3, c = bc & 7;
    int l0 = LY[ti] * 64, s0 = SX[ti] * 64;

    int t = threadIdx.x, ty = t >> 4, tx = t & 15;
    int arow = t >> 3, akc4 = (t & 7) * 4;

    const float* c_base = Cm + (size_t)(b * L + c * CS + l0) * NS;
    const float* b_base = Bm + (size_t)(b * L + c * CS + s0) * NS;

#pragma unroll
    for (int i = 0; i < 2; i++) {
        cpa16(&Cs[0][arow + 32 * i][akc4],  c_base + (size_t)(arow + 32 * i) * NS + akc4);
        cpa16(&Bs2[0][arow + 32 * i][akc4], b_base + (size_t)(arow + 32 * i) * NS + akc4);
    }
    CP_COMMIT();

    float2 acc2[4][4];
#pragma unroll
    for (int i = 0; i < 4; i++)
#pragma unroll
        for (int j = 0; j < 4; j++) acc2[i][j] = make_float2(0.f, 0.f);

    for (int kt = 0; kt < 4; kt++) {
        int cur = kt & 1;
        if (kt + 1 < 4) {
            int nb = cur ^ 1, off = (kt + 1) * 32;
#pragma unroll
            for (int i = 0; i < 2; i++) {
                cpa16(&Cs[nb][arow + 32 * i][akc4],  c_base + (size_t)(arow + 32 * i) * NS + off + akc4);
                cpa16(&Bs2[nb][arow + 32 * i][akc4], b_base + (size_t)(arow + 32 * i) * NS + off + akc4);
            }
            CP_COMMIT();
            CP_WAIT1();
        } else {
            CP_WAIT0();
        }
        __syncthreads();
#pragma unroll
        for (int k = 0; k < 32; k += 2) {
            float2 a2[4], b2[4];
#pragma unroll
            for (int i = 0; i < 4; i++) a2[i] = *(const float2*)&Cs[cur][ty + 16 * i][k];
#pragma unroll
            for (int j = 0; j < 4; j++) b2[j] = *(const float2*)&Bs2[cur][tx + 16 * j][k];
#pragma unroll
            for (int i = 0; i < 4; i++)
#pragma unroll
                for (int j = 0; j < 4; j++) acc2[i][j] = fma2(a2[i], b2[j], acc2[i][j]);
        }
        __syncthreads();
    }
    size_t cb = ((size_t)bc) * CS * CS;
#pragma unroll
    for (int i = 0; i < 4; i++)
#pragma unroll
        for (int j = 0; j < 4; j++)
            g_CB[cb + (size_t)(l0 + ty + 16 * i) * CS + s0 + tx + 16 * j] =
                acc2[i][j].x + acc2[i][j].y;
}

// ---------------- K5: chunk_scan (inter + masked intra + epilogue) --------
__global__ void __launch_bounds__(256, 2) k_scan(const float* __restrict__ x,
                                                 const float* __restrict__ Cm,
                                                 const float* __restrict__ z,
                                                 const float* __restrict__ D,
                                                 float* __restrict__ out) {
    extern __shared__ __align__(16) float smp[];
    float (*As)[128][36] = (float(*)[128][36])smp;
    float (*Bs)[64][36]  = (float(*)[64][36])(smp + 2 * 128 * 36);
    float* sdall = smp + 2 * 128 * 36 + 2 * 64 * 36;   // 256
    float* sd2   = sdall + 256;                        // 256

    int tmp = blockIdx.x;
    int lt = tmp & 1; tmp >>= 1;
    int h = tmp % H;  tmp /= H;
    int c = tmp % NC;
    int b = tmp / NC;
    int bc = b * NC + c;
    int l0 = lt * 128;

    int t = threadIdx.x, ty = t >> 4, tx = t & 15;
    int dbase = ((b * H + h) * NC + c) * CS;
    float dv = g_dacs[dbase + t];
    sdall[t] = dv;
    sd2[t] = dv * LOG2E;

    int arow = t >> 3, akc4 = (t & 7) * 4;

    // ---------- Phase A: acc = C[l,:] . prev[(h,p),:], K = 128 -------------
    const float* c_base = Cm + (size_t)(b * L + c * CS + l0) * NS;
    const float* p_base = g_prev + (size_t)bc * H * P * NS + (size_t)(h * 64) * NS;

#pragma unroll
    for (int i = 0; i < 4; i++)
        cpa16(&As[0][arow + 32 * i][akc4], c_base + (size_t)(arow + 32 * i) * NS + akc4);
#pragma unroll
    for (int i = 0; i < 2; i++)
        cpa16(&Bs[0][arow + 32 * i][akc4], p_base + (size_t)(arow + 32 * i) * NS + akc4);
    CP_COMMIT();

    float2 acc2[8][4];
#pragma unroll
    for (int i = 0; i < 8; i++)
#pragma unroll
        for (int j = 0; j < 4; j++) acc2[i][j] = make_float2(0.f, 0.f);

    for (int kt = 0; kt < 4; kt++) {
        int cur = kt & 1;
        if (kt + 1 < 4) {
            int nb = cur ^ 1, off = (kt + 1) * 32;
#pragma unroll
            for (int i = 0; i < 4; i++)
                cpa16(&As[nb][arow + 32 * i][akc4], c_base + (size_t)(arow + 32 * i) * NS + off + akc4);
#pragma unroll
            for (int i = 0; i < 2; i++)
                cpa16(&Bs[nb][arow + 32 * i][akc4], p_base + (size_t)(arow + 32 * i) * NS + off + akc4);
            CP_COMMIT();
            CP_WAIT1();
        } else {
            CP_WAIT0();
        }
        __syncthreads();
#pragma unroll
        for (int k = 0; k < 32; k += 2) {
            float2 a2[8], b2[4];
#pragma unroll
            for (int i = 0; i < 8; i++) a2[i] = *(const float2*)&As[cur][ty * 8 + i][k];
#pragma unroll
            for (int j = 0; j < 4; j++) b2[j] = *(const float2*)&Bs[cur][tx + 16 * j][k];
#pragma unroll
            for (int i = 0; i < 8; i++)
#pragma unroll
                for (int j = 0; j < 4; j++) acc2[i][j] = fma2(a2[i], b2[j], acc2[i][j]);
        }
        __syncthreads();
    }
    // scale inter term by exp(dacs[l]) = ex2(sd2[l])
#pragma unroll
    for (int i = 0; i < 8; i++) {
        float el = ex2(sd2[l0 + ty * 8 + i]);
#pragma unroll
        for (int j = 0; j < 4; j++) { acc2[i][j].x *= el; acc2[i][j].y *= el; }
    }

    // ---------- Phase B: masked intra scores @ (x*dt), K = s ---------------
    const float* cb_base = g_CB + (size_t)bc * CS * CS + (size_t)l0 * CS;
    const float* x_base  = g_xw2 + ((size_t)b * 4096 + h * 64) * L + c * CS;
    int nkt = (lt == 0) ? 4 : 8;
    int tr = t >> 1, tk0 = (t & 1) * 16;
    int lr = l0 + tr;
    float dlr2 = sd2[lr];

#pragma unroll
    for (int i = 0; i < 4; i++)
        cpa16(&As[0][arow + 32 * i][akc4], cb_base + (size_t)(arow + 32 * i) * CS + akc4);
#pragma unroll
    for (int i = 0; i < 2; i++)
        cpa16(&Bs[0][arow + 32 * i][akc4], x_base + (size_t)(arow + 32 * i) * L + akc4);
    CP_COMMIT();

    for (int kt = 0; kt < nkt; kt++) {
        int cur = kt & 1;
        int s0 = kt * 32;
        if (kt + 1 < nkt) {
            int nb = cur ^ 1, off = s0 + 32;
#pragma unroll
            for (int i = 0; i < 4; i++)
                cpa16(&As[nb][arow + 32 * i][akc4], cb_base + (size_t)(arow + 32 * i) * CS + off + akc4);
#pragma unroll
            for (int i = 0; i < 2; i++)
                cpa16(&Bs[nb][arow + 32 * i][akc4], x_base + (size_t)(arow + 32 * i) * L + off + akc4);
            CP_COMMIT();
            CP_WAIT1();
        } else {
            CP_WAIT0();
        }
        __syncthreads();
        // transform raw CB tile in place: v *= exp(dacs[l]-dacs[s]); mask s>l
#pragma unroll
        for (int i = 0; i < 4; i++) {
            int k = tk0 + 4 * i;
            int s = s0 + k;
            float4 v = *(float4*)&As[cur][tr][k];
            v.x = (s     <= lr) ? v.x * ex2(dlr2 - sd2[s])     : 0.f;
            v.y = (s + 1 <= lr) ? v.y * ex2(dlr2 - sd2[s + 1]) : 0.f;
            v.z = (s + 2 <= lr) ? v.z * ex2(dlr2 - sd2[s + 2]) : 0.f;
            v.w = (s + 3 <= lr) ? v.w * ex2(dlr2 - sd2[s + 3]) : 0.f;
            *(float4*)&As[cur][tr][k] = v;
        }
        __syncthreads();
#pragma unroll
        for (int k = 0; k < 32; k += 2) {
            float2 a2[8], b2[4];
#pragma unroll
            for (int i = 0; i < 8; i++) a2[i] = *(const float2*)&As[cur][ty * 8 + i][k];
#pragma unroll
            for (int j = 0; j < 4; j++) b2[j] = *(const float2*)&Bs[cur][tx + 16 * j][k];
#pragma unroll
            for (int i = 0; i < 8; i++)
#pragma unroll
                for (int j = 0; j < 4; j++) acc2[i][j] = fma2(a2[i], b2[j], acc2[i][j]);
        }
        __syncthreads();
    }

    // Epilogue: fold k-parity, + x*D, * silu(z)
    float Dh = D[h];
#pragma unroll
    for (int i = 0; i < 8; i++) {
#pragma unroll
        for (int j = 0; j < 4; j++) {
            int l = l0 + ty * 8 + i, p = tx + 16 * j;
            size_t gi = (((size_t)b * L + c * CS + l) * H + h) * P + p;
            float xv = x[gi], zv = z[gi];
            float o = acc2[i][j].x + acc2[i][j].y + xv * Dh;
            float sil = zv / (1.f + __expf(-zv));
            out[gi] = o * sil;
        }
    }
}

// ---------------- launch ----------------------------------------------------
extern "C" void kernel_launch(void* const* d_in, const int* in_sizes, int n_in,
                              void* d_out, int out_size) {
    const float* x   = (const float*)d_in[0];
    const float* dt  = (const float*)d_in[1];
    const float* A   = (const float*)d_in[2];
    const float* Bm  = (const float*)d_in[3];
    const float* Cm  = (const float*)d_in[4];
    const float* D   = (const float*)d_in[5];
    const float* z   = (const float*)d_in[6];
    const float* dtb = (const float*)d_in[7];
    (void)in_sizes; (void)n_in;

    float* out = (float*)d_out;
    const int OUT_ELEMS = Bb * L * H * P;
    const int FIN_ELEMS = Bb * H * P * NS;
    float* finals = (out_size >= OUT_ELEMS + FIN_ELEMS) ? (out + OUT_ELEMS) : nullptr;

    static int attr_done = 0;
    if (!attr_done) {
        cudaFuncSetAttribute(k_state2, cudaFuncAttributeMaxDynamicSharedMemorySize, SMEM_ST);
        cudaFuncSetAttribute(k_scan,   cudaFuncAttributeMaxDynamicSharedMemorySize, SMEM_SC);
        attr_done = 1;
    }

    k_dt    <<<Bb * H * NC, CS>>>(dt, A, dtb);
    dim3 gxw(128, 8, Bb * NC);
    k_xw    <<<gxw, dim3(32, 8)>>>(x);
    dim3 gbt(4, 8, Bb * NC);
    k_Bt    <<<gbt, dim3(32, 8)>>>(Bm);
    k_state2<<<Bb * NC * 32 * 2, 256, SMEM_ST>>>();
    k_pass  <<<Bb * H * 32, 256>>>(finals);
    k_cb    <<<Bb * NC * 10, 256>>>(Cm, Bm);
    k_scan  <<<Bb * NC * H * 2, 256, SMEM_SC>>>(x, Cm, z, D, out);
}